// round 1
// baseline (speedup 1.0000x reference)
#include <cuda_runtime.h>

#define N_TX   500000
#define N_ACC  100000
#define NE     1000000
#define D_ACC  32
#define D_TX   64
#define HDIM   64

// Scratch: per-tx aggregation sum (32-d) and degree count.
__device__ __align__(16) float g_agg[(size_t)N_TX * D_ACC];   // 64 MB
__device__ __align__(16) float g_deg[N_TX];                   // 2 MB

// ---------------------------------------------------------------------------
// Kernel 1: zero the scratch buffers (float4 stores)
// ---------------------------------------------------------------------------
__global__ void zero_kernel() {
    int i = blockIdx.x * blockDim.x + threadIdx.x;
    const int n_agg4 = (N_TX * D_ACC) / 4;   // 4,000,000
    const int n_deg4 = N_TX / 4;             // 125,000
    float4 z = make_float4(0.f, 0.f, 0.f, 0.f);
    if (i < n_agg4) {
        ((float4*)g_agg)[i] = z;
    } else if (i < n_agg4 + n_deg4) {
        ((float4*)g_deg)[i - n_agg4] = z;
    }
}

// ---------------------------------------------------------------------------
// Kernel 2: edge scatter. 8 lanes per edge, each lane handles one float4 of
// the 32-d x_acc row. red.global.add.v4.f32 (sm_90+) quarters atomic op count.
// ---------------------------------------------------------------------------
__global__ void scatter_kernel(const float* __restrict__ x_acc,
                               const int*   __restrict__ src_idx,
                               const int*   __restrict__ dst_idx) {
    unsigned gid = blockIdx.x * blockDim.x + threadIdx.x;
    if (gid >= (unsigned)NE * 8u) return;
    unsigned e = gid >> 3;
    unsigned c = gid & 7u;
    int src = src_idx[e];
    int dst = dst_idx[e];
    float4 v = ((const float4*)x_acc)[src * 8 + c];
    float* p = g_agg + (size_t)dst * D_ACC + c * 4;
    asm volatile("red.global.add.v4.f32 [%0], {%1, %2, %3, %4};"
                 :: "l"(p), "f"(v.x), "f"(v.y), "f"(v.z), "f"(v.w)
                 : "memory");
    if (c == 0) {
        float one = 1.0f;
        asm volatile("red.global.add.f32 [%0], %1;"
                     :: "l"(g_deg + dst), "f"(one) : "memory");
    }
}

// ---------------------------------------------------------------------------
// Kernel 3: fused  h = [x_tx | agg_mean] @ [Wr ; Wl] + bl ; relu ; W_out dot
// Tile: 56 rows x 64 cols per block, 224 threads, thread = (row, 16-col group).
// Inner product uses packed fma.rn.f32x2 (FFMA2) for 2x FFMA throughput.
// ---------------------------------------------------------------------------
#define TROWS    56
#define CTHREADS 224
#define XS_STRIDE 97   // 97 % 32 == 1 -> conflict-free per-k row reads

__global__ __launch_bounds__(CTHREADS)
void compute_kernel(const float* __restrict__ x_tx,
                    const float* __restrict__ Wl,   // [32,64]
                    const float* __restrict__ bl,   // [64]
                    const float* __restrict__ Wr,   // [64,64]
                    const float* __restrict__ Wout, // [64]
                    const float* __restrict__ bout, // [1]
                    float* __restrict__ out) {
    __shared__ __align__(16) float Ws[96 * 64];           // rows 0..63 = Wr, 64..95 = Wl
    __shared__ __align__(16) float bl_s[64];
    __shared__ __align__(16) float wout_s[64];
    __shared__ __align__(16) float xs[TROWS * XS_STRIDE]; // per-row: 64 x | 32 agg_mean

    const int tid = threadIdx.x;
    const int r0  = blockIdx.x * TROWS;

    // Stage weights
    for (int i = tid; i < 64 * 64; i += CTHREADS) Ws[i] = Wr[i];
    for (int i = tid; i < 32 * 64; i += CTHREADS) Ws[64 * 64 + i] = Wl[i];
    if (tid < 64) { bl_s[tid] = bl[tid]; wout_s[tid] = Wout[tid]; }

    // Stage x_tx tile
    for (int i = tid; i < TROWS * 16; i += CTHREADS) {
        int rt = i >> 4, j = i & 15;
        int r = r0 + rt;
        float4 v = make_float4(0.f, 0.f, 0.f, 0.f);
        if (r < N_TX) v = ((const float4*)x_tx)[r * 16 + j];
        float* d = &xs[rt * XS_STRIDE + j * 4];
        d[0] = v.x; d[1] = v.y; d[2] = v.z; d[3] = v.w;
    }
    // Stage agg tile with mean applied (divide by clamped degree)
    for (int i = tid; i < TROWS * 8; i += CTHREADS) {
        int rt = i >> 3, j = i & 7;
        int r = r0 + rt;
        float4 v = make_float4(0.f, 0.f, 0.f, 0.f);
        if (r < N_TX) {
            float s = 1.0f / fmaxf(g_deg[r], 1.0f);
            float4 a = ((const float4*)g_agg)[r * 8 + j];
            v = make_float4(a.x * s, a.y * s, a.z * s, a.w * s);
        }
        float* d = &xs[rt * XS_STRIDE + 64 + j * 4];
        d[0] = v.x; d[1] = v.y; d[2] = v.z; d[3] = v.w;
    }
    __syncthreads();

    const int rt = tid >> 2;       // row within tile
    const int cg = tid & 3;        // 16-col group
    const int r  = r0 + rt;

    // Accumulators as packed f32x2 (bit pattern in u64), init with bias pairs
    unsigned long long acc[8];
    {
        const double* blD = (const double*)bl_s;
        #pragma unroll
        for (int j = 0; j < 8; j++)
            acc[j] = __double_as_longlong(blD[cg * 8 + j]);
    }

    const float* xrow = &xs[rt * XS_STRIDE];
    #pragma unroll 8
    for (int k = 0; k < 96; k++) {
        float xv = xrow[k];
        unsigned long long xd;
        asm("mov.b64 %0, {%1, %1};" : "=l"(xd) : "f"(xv));
        const double2* wp = (const double2*)(Ws + k * 64 + cg * 16);
        #pragma unroll
        for (int jj = 0; jj < 4; jj++) {
            double2 w = wp[jj];
            unsigned long long w0 = __double_as_longlong(w.x);
            unsigned long long w1 = __double_as_longlong(w.y);
            asm("fma.rn.f32x2 %0, %1, %2, %0;" : "+l"(acc[2 * jj])     : "l"(xd), "l"(w0));
            asm("fma.rn.f32x2 %0, %1, %2, %0;" : "+l"(acc[2 * jj + 1]) : "l"(xd), "l"(w1));
        }
    }

    // Epilogue: relu, store tx_x, partial logit dot
    float partial = 0.0f;
    if (r < N_TX) {
        float h[16];
        #pragma unroll
        for (int j = 0; j < 8; j++) {
            float lo, hi;
            asm("mov.b64 {%0, %1}, %2;" : "=f"(lo), "=f"(hi) : "l"(acc[j]));
            h[2 * j]     = fmaxf(lo, 0.0f);
            h[2 * j + 1] = fmaxf(hi, 0.0f);
        }
        float4* ox = (float4*)(out + N_TX + (size_t)r * HDIM + cg * 16);
        ox[0] = make_float4(h[0],  h[1],  h[2],  h[3]);
        ox[1] = make_float4(h[4],  h[5],  h[6],  h[7]);
        ox[2] = make_float4(h[8],  h[9],  h[10], h[11]);
        ox[3] = make_float4(h[12], h[13], h[14], h[15]);
        #pragma unroll
        for (int j = 0; j < 16; j++) partial += h[j] * wout_s[cg * 16 + j];
    }
    // 4-lane (col-group) reduction; groups are validity-uniform, all lanes shfl
    partial += __shfl_xor_sync(0xffffffffu, partial, 1);
    partial += __shfl_xor_sync(0xffffffffu, partial, 2);
    if (cg == 0 && r < N_TX) out[r] = partial + bout[0];
}

// ---------------------------------------------------------------------------
extern "C" void kernel_launch(void* const* d_in, const int* in_sizes, int n_in,
                              void* d_out, int out_size) {
    const float* x_tx     = (const float*)d_in[0];
    const float* x_acc    = (const float*)d_in[1];
    const int*   pays_src = (const int*)d_in[2];
    const int*   pays_dst = (const int*)d_in[3];
    // d_in[4], d_in[5]: rev edges — dead code in the reference (h_acc unused)
    const float* Wl_pays  = (const float*)d_in[6];
    const float* bl_pays  = (const float*)d_in[7];
    const float* Wr_pays  = (const float*)d_in[8];
    // d_in[9..11]: rev weights — unused
    const float* W_out    = (const float*)d_in[12];
    const float* b_out    = (const float*)d_in[13];
    float* out = (float*)d_out;   // [logits(500000) | tx_x(500000*64)]

    const int n_zero = (N_TX * D_ACC) / 4 + N_TX / 4;
    zero_kernel<<<(n_zero + 255) / 256, 256>>>();
    scatter_kernel<<<(NE * 8) / 256, 256>>>(x_acc, pays_src, pays_dst);
    compute_kernel<<<(N_TX + TROWS - 1) / TROWS, CTHREADS>>>(
        x_tx, Wl_pays, bl_pays, Wr_pays, W_out, b_out, out);
}

// round 2
// speedup vs baseline: 1.0487x; 1.0487x over previous
#include <cuda_runtime.h>

#define N_TX   500000
#define N_ACC  100000
#define NE     1000000
#define D_ACC  32
#define D_TX   64
#define HDIM   64

#define SCAN_BS   1024
#define N_SCAN_BLKS ((N_TX + SCAN_BS - 1) / SCAN_BS)   // 489

// CSR scratch (int only; no big float scratch, no float atomics)
__device__ int g_deg[N_TX];
__device__ int g_off[N_TX];
__device__ int g_cursor[N_TX];
__device__ int g_sorted_src[NE];
__device__ int g_bsum[SCAN_BS];

// ---------------------------------------------------------------------------
// K1: zero deg + cursor (4 MB)
// ---------------------------------------------------------------------------
__global__ void zero_kernel() {
    int i = blockIdx.x * blockDim.x + threadIdx.x;
    if (i < N_TX) { g_deg[i] = 0; g_cursor[i] = 0; }
}

// ---------------------------------------------------------------------------
// K2: degree histogram over dst
// ---------------------------------------------------------------------------
__global__ void hist_kernel(const int* __restrict__ dst_idx) {
    int e = blockIdx.x * blockDim.x + threadIdx.x;
    if (e < NE) atomicAdd(&g_deg[dst_idx[e]], 1);
}

// ---------------------------------------------------------------------------
// K3a: per-block exclusive scan (Hillis-Steele), block totals to g_bsum
// ---------------------------------------------------------------------------
__global__ void scan1_kernel() {
    __shared__ int sh[SCAN_BS];
    int t = threadIdx.x;
    int idx = blockIdx.x * SCAN_BS + t;
    int v = (idx < N_TX) ? g_deg[idx] : 0;
    sh[t] = v;
    __syncthreads();
    #pragma unroll
    for (int o = 1; o < SCAN_BS; o <<= 1) {
        int add = (t >= o) ? sh[t - o] : 0;
        __syncthreads();
        sh[t] += add;
        __syncthreads();
    }
    if (idx < N_TX) g_off[idx] = sh[t] - v;          // exclusive
    if (t == SCAN_BS - 1) g_bsum[blockIdx.x] = sh[t]; // block total
}

// ---------------------------------------------------------------------------
// K3b: single-block exclusive scan of block sums (489 <= 1024)
// ---------------------------------------------------------------------------
__global__ void scan2_kernel() {
    __shared__ int sh[SCAN_BS];
    int t = threadIdx.x;
    int v = (t < N_SCAN_BLKS) ? g_bsum[t] : 0;
    sh[t] = v;
    __syncthreads();
    #pragma unroll
    for (int o = 1; o < SCAN_BS; o <<= 1) {
        int add = (t >= o) ? sh[t - o] : 0;
        __syncthreads();
        sh[t] += add;
        __syncthreads();
    }
    if (t < N_SCAN_BLKS) g_bsum[t] = sh[t] - v;       // exclusive
}

// ---------------------------------------------------------------------------
// K3c: add scanned block offsets
// ---------------------------------------------------------------------------
__global__ void scan3_kernel() {
    int idx = blockIdx.x * SCAN_BS + threadIdx.x;
    if (idx < N_TX) g_off[idx] += g_bsum[blockIdx.x];
}

// ---------------------------------------------------------------------------
// K4: place src ids into CSR slots
// ---------------------------------------------------------------------------
__global__ void place_kernel(const int* __restrict__ src_idx,
                             const int* __restrict__ dst_idx) {
    int e = blockIdx.x * blockDim.x + threadIdx.x;
    if (e >= NE) return;
    int d = dst_idx[e];
    int pos = g_off[d] + atomicAdd(&g_cursor[d], 1);
    g_sorted_src[pos] = src_idx[e];
}

// ---------------------------------------------------------------------------
// K5: fused gather-mean + [x_tx | agg] @ [Wr ; Wl] + bl ; relu ; W_out dot.
// Tile: 56 rows x 64 cols, 224 threads, thread = (row, 16-col group).
// Packed fma.rn.f32x2 inner product (2x FFMA rate).
// ---------------------------------------------------------------------------
#define TROWS    56
#define CTHREADS 224
#define XS_STRIDE 97

__global__ __launch_bounds__(CTHREADS)
void compute_kernel(const float* __restrict__ x_tx,
                    const float* __restrict__ x_acc,
                    const float* __restrict__ Wl,   // [32,64]
                    const float* __restrict__ bl,   // [64]
                    const float* __restrict__ Wr,   // [64,64]
                    const float* __restrict__ Wout, // [64]
                    const float* __restrict__ bout, // [1]
                    float* __restrict__ out) {
    __shared__ __align__(16) float Ws[96 * 64];           // rows 0..63 = Wr, 64..95 = Wl
    __shared__ __align__(16) float bl_s[64];
    __shared__ __align__(16) float wout_s[64];
    __shared__ __align__(16) float xs[TROWS * XS_STRIDE]; // per row: 64 x | 32 agg_mean

    const int tid = threadIdx.x;
    const int r0  = blockIdx.x * TROWS;
    const int rt  = tid >> 2;
    const int cg  = tid & 3;
    const int r   = r0 + rt;

    // Stage weights / bias
    for (int i = tid; i < 64 * 64; i += CTHREADS) Ws[i] = Wr[i];
    for (int i = tid; i < 32 * 64; i += CTHREADS) Ws[64 * 64 + i] = Wl[i];
    if (tid < 64) { bl_s[tid] = bl[tid]; wout_s[tid] = Wout[tid]; }

    // Stage x_tx tile (float4)
    for (int i = tid; i < TROWS * 16; i += CTHREADS) {
        int rr = i >> 4, j = i & 15;
        int row = r0 + rr;
        float4 v = make_float4(0.f, 0.f, 0.f, 0.f);
        if (row < N_TX) v = ((const float4*)x_tx)[row * 16 + j];
        float* d = &xs[rr * XS_STRIDE + j * 4];
        d[0] = v.x; d[1] = v.y; d[2] = v.z; d[3] = v.w;
    }

    // CSR gather-mean: 4 threads per row, each covers 8 of 32 agg dims
    {
        int cnt = 0, start = 0;
        if (r < N_TX) { cnt = g_deg[r]; start = g_off[r]; }
        float a0 = 0.f, a1 = 0.f, a2 = 0.f, a3 = 0.f;
        float a4 = 0.f, a5 = 0.f, a6 = 0.f, a7 = 0.f;
        for (int i = 0; i < cnt; i++) {
            int s = g_sorted_src[start + i];
            const float4* p = (const float4*)(x_acc + (size_t)s * D_ACC) + cg * 2;
            float4 v0 = p[0], v1 = p[1];
            a0 += v0.x; a1 += v0.y; a2 += v0.z; a3 += v0.w;
            a4 += v1.x; a5 += v1.y; a6 += v1.z; a7 += v1.w;
        }
        float inv = 1.0f / (float)max(cnt, 1);
        float* d = &xs[rt * XS_STRIDE + 64 + cg * 8];
        d[0] = a0 * inv; d[1] = a1 * inv; d[2] = a2 * inv; d[3] = a3 * inv;
        d[4] = a4 * inv; d[5] = a5 * inv; d[6] = a6 * inv; d[7] = a7 * inv;
    }
    __syncthreads();

    // Accumulators as packed f32x2, seeded with bias pairs
    unsigned long long acc[8];
    {
        const double* blD = (const double*)bl_s;
        #pragma unroll
        for (int j = 0; j < 8; j++)
            acc[j] = __double_as_longlong(blD[cg * 8 + j]);
    }

    const float* xrow = &xs[rt * XS_STRIDE];
    #pragma unroll 8
    for (int k = 0; k < 96; k++) {
        float xv = xrow[k];
        unsigned long long xd;
        asm("mov.b64 %0, {%1, %1};" : "=l"(xd) : "f"(xv));
        const double2* wp = (const double2*)(Ws + k * 64 + cg * 16);
        #pragma unroll
        for (int jj = 0; jj < 4; jj++) {
            double2 w = wp[jj];
            unsigned long long w0 = __double_as_longlong(w.x);
            unsigned long long w1 = __double_as_longlong(w.y);
            asm("fma.rn.f32x2 %0, %1, %2, %0;" : "+l"(acc[2 * jj])     : "l"(xd), "l"(w0));
            asm("fma.rn.f32x2 %0, %1, %2, %0;" : "+l"(acc[2 * jj + 1]) : "l"(xd), "l"(w1));
        }
    }

    // Epilogue: relu, store tx_x, partial logit dot
    float partial = 0.0f;
    if (r < N_TX) {
        float h[16];
        #pragma unroll
        for (int j = 0; j < 8; j++) {
            float lo, hi;
            asm("mov.b64 {%0, %1}, %2;" : "=f"(lo), "=f"(hi) : "l"(acc[j]));
            h[2 * j]     = fmaxf(lo, 0.0f);
            h[2 * j + 1] = fmaxf(hi, 0.0f);
        }
        float4* ox = (float4*)(out + N_TX + (size_t)r * HDIM + cg * 16);
        ox[0] = make_float4(h[0],  h[1],  h[2],  h[3]);
        ox[1] = make_float4(h[4],  h[5],  h[6],  h[7]);
        ox[2] = make_float4(h[8],  h[9],  h[10], h[11]);
        ox[3] = make_float4(h[12], h[13], h[14], h[15]);
        #pragma unroll
        for (int j = 0; j < 16; j++) partial += h[j] * wout_s[cg * 16 + j];
    }
    partial += __shfl_xor_sync(0xffffffffu, partial, 1);
    partial += __shfl_xor_sync(0xffffffffu, partial, 2);
    if (cg == 0 && r < N_TX) out[r] = partial + bout[0];
}

// ---------------------------------------------------------------------------
extern "C" void kernel_launch(void* const* d_in, const int* in_sizes, int n_in,
                              void* d_out, int out_size) {
    const float* x_tx     = (const float*)d_in[0];
    const float* x_acc    = (const float*)d_in[1];
    const int*   pays_src = (const int*)d_in[2];
    const int*   pays_dst = (const int*)d_in[3];
    // d_in[4], d_in[5]: rev edges — dead code in reference (h_acc unused)
    const float* Wl_pays  = (const float*)d_in[6];
    const float* bl_pays  = (const float*)d_in[7];
    const float* Wr_pays  = (const float*)d_in[8];
    // d_in[9..11]: rev weights — unused
    const float* W_out    = (const float*)d_in[12];
    const float* b_out    = (const float*)d_in[13];
    float* out = (float*)d_out;   // [logits(500000) | tx_x(500000*64)]

    zero_kernel<<<(N_TX + 255) / 256, 256>>>();
    hist_kernel<<<(NE + 255) / 256, 256>>>(pays_dst);
    scan1_kernel<<<N_SCAN_BLKS, SCAN_BS>>>();
    scan2_kernel<<<1, SCAN_BS>>>();
    scan3_kernel<<<N_SCAN_BLKS, SCAN_BS>>>();
    place_kernel<<<(NE + 255) / 256, 256>>>(pays_src, pays_dst);
    compute_kernel<<<(N_TX + TROWS - 1) / TROWS, CTHREADS>>>(
        x_tx, x_acc, Wl_pays, bl_pays, Wr_pays, W_out, b_out, out);
}

// round 3
// speedup vs baseline: 2.3893x; 2.2783x over previous
#include <cuda_runtime.h>

#define N_TX   500000
#define N_ACC  100000
#define NE     1000000
#define D_ACC  32
#define D_TX   64
#define HDIM   64

#define SCAN_BS   1024
#define N_SCAN_BLKS ((N_TX + SCAN_BS - 1) / SCAN_BS)   // 489

// CSR scratch
__device__ int g_deg[N_TX];
__device__ int g_off[N_TX];      // exclusive offsets; mutated to end-ptrs by place
__device__ int g_sorted_src[NE];
__device__ int g_bsum[SCAN_BS];

// ---------------------------------------------------------------------------
__global__ void zero_kernel() {
    int i = blockIdx.x * blockDim.x + threadIdx.x;
    if (i < N_TX) g_deg[i] = 0;
}

__global__ void hist_kernel(const int* __restrict__ dst_idx) {
    int e = blockIdx.x * blockDim.x + threadIdx.x;
    if (e < NE) atomicAdd(&g_deg[dst_idx[e]], 1);
}

__global__ void scan1_kernel() {
    __shared__ int sh[SCAN_BS];
    int t = threadIdx.x;
    int idx = blockIdx.x * SCAN_BS + t;
    int v = (idx < N_TX) ? g_deg[idx] : 0;
    sh[t] = v;
    __syncthreads();
    #pragma unroll
    for (int o = 1; o < SCAN_BS; o <<= 1) {
        int add = (t >= o) ? sh[t - o] : 0;
        __syncthreads();
        sh[t] += add;
        __syncthreads();
    }
    if (idx < N_TX) g_off[idx] = sh[t] - v;
    if (t == SCAN_BS - 1) g_bsum[blockIdx.x] = sh[t];
}

__global__ void scan2_kernel() {
    __shared__ int sh[SCAN_BS];
    int t = threadIdx.x;
    int v = (t < N_SCAN_BLKS) ? g_bsum[t] : 0;
    sh[t] = v;
    __syncthreads();
    #pragma unroll
    for (int o = 1; o < SCAN_BS; o <<= 1) {
        int add = (t >= o) ? sh[t - o] : 0;
        __syncthreads();
        sh[t] += add;
        __syncthreads();
    }
    if (t < N_SCAN_BLKS) g_bsum[t] = sh[t] - v;
}

__global__ void scan3_kernel() {
    int idx = blockIdx.x * SCAN_BS + threadIdx.x;
    if (idx < N_TX) g_off[idx] += g_bsum[blockIdx.x];
}

// place: bump g_off directly (it becomes the END pointer; start = end - deg)
__global__ void place_kernel(const int* __restrict__ src_idx,
                             const int* __restrict__ dst_idx) {
    int e = blockIdx.x * blockDim.x + threadIdx.x;
    if (e >= NE) return;
    int pos = atomicAdd(&g_off[dst_idx[e]], 1);
    g_sorted_src[pos] = src_idx[e];
}

// ---------------------------------------------------------------------------
// Fused kernel: gather-mean + [x|agg] @ [Wr;Wl] + bl ; relu ; W_out dot.
// 128 rows / block, 128 threads. Thread owns a 4-row x 16-col output tile.
// xs_T is K-major (transposed) so 4 consecutive rows load as one LDS.128.
// Per thread per k: 5 LDS.128 -> 64 FMAs (32 fma.rn.f32x2).
// ---------------------------------------------------------------------------
#define RBLK     128
#define CTHREADS 128

__global__ __launch_bounds__(CTHREADS, 3)
void compute_kernel(const float* __restrict__ x_tx,
                    const float* __restrict__ x_acc,
                    const float* __restrict__ Wl,   // [32,64]
                    const float* __restrict__ bl,   // [64]
                    const float* __restrict__ Wr,   // [64,64]
                    const float* __restrict__ Wout, // [64]
                    const float* __restrict__ bout, // [1]
                    float* __restrict__ out) {
    extern __shared__ float smem[];
    float* Ws = smem;               // [96][64]  rows 0..63 = Wr, 64..95 = Wl
    float* xsT = smem + 96 * 64;    // [96][128] K-major: xsT[k][row]
    __shared__ float bl_s[64];
    __shared__ float wout_s[64];

    const int tid = threadIdx.x;
    const int r0  = blockIdx.x * RBLK;

    // Stage weights
    for (int i = tid; i < 64 * 64; i += CTHREADS) Ws[i] = Wr[i];
    for (int i = tid; i < 32 * 64; i += CTHREADS) Ws[64 * 64 + i] = Wl[i];
    if (tid < 64) { bl_s[tid] = bl[tid]; wout_s[tid] = Wout[tid]; }

    // Stage x_tx transposed: thread t owns row r0+t; writes are lane-consecutive
    {
        int r = r0 + tid;
        if (r < N_TX) {
            const float4* xr = (const float4*)(x_tx + (size_t)r * D_TX);
            #pragma unroll
            for (int j = 0; j < 16; j++) {
                float4 v = xr[j];
                xsT[(j * 4 + 0) * RBLK + tid] = v.x;
                xsT[(j * 4 + 1) * RBLK + tid] = v.y;
                xsT[(j * 4 + 2) * RBLK + tid] = v.z;
                xsT[(j * 4 + 3) * RBLK + tid] = v.w;
            }
        } else {
            #pragma unroll
            for (int k = 0; k < 64; k++) xsT[k * RBLK + tid] = 0.0f;
        }
    }

    // CSR gather-mean: thread t aggregates row r0+t (all 32 dims in regs)
    {
        int r = r0 + tid;
        float a[32];
        #pragma unroll
        for (int d = 0; d < 32; d++) a[d] = 0.0f;
        int cnt = 0;
        if (r < N_TX) {
            int end = g_off[r];          // end pointer after place
            cnt = g_deg[r];
            int start = end - cnt;
            for (int i = 0; i < cnt; i++) {
                int s = g_sorted_src[start + i];
                const float4* p = (const float4*)(x_acc + (size_t)s * D_ACC);
                #pragma unroll
                for (int j = 0; j < 8; j++) {
                    float4 v = p[j];
                    a[j * 4 + 0] += v.x; a[j * 4 + 1] += v.y;
                    a[j * 4 + 2] += v.z; a[j * 4 + 3] += v.w;
                }
            }
        }
        float inv = 1.0f / (float)max(cnt, 1);
        #pragma unroll
        for (int d = 0; d < 32; d++)
            xsT[(64 + d) * RBLK + tid] = a[d] * inv;
    }
    __syncthreads();

    const int rq = tid >> 2;   // 0..31 : row quad (rows rq*4 .. rq*4+3)
    const int cg = tid & 3;    // 16-col group

    // 4 rows x 8 col-pairs of packed f32x2 accumulators, seeded with bias
    unsigned long long acc[4][8];
    {
        const double* blD = (const double*)bl_s;
        #pragma unroll
        for (int jj = 0; jj < 8; jj++) {
            unsigned long long b = __double_as_longlong(blD[cg * 8 + jj]);
            acc[0][jj] = b; acc[1][jj] = b; acc[2][jj] = b; acc[3][jj] = b;
        }
    }

    const float* xcol = xsT + rq * 4;
    const double2* wbase = (const double2*)(Ws + cg * 16);

    #pragma unroll 4
    for (int k = 0; k < 96; k++) {
        float4 xv = *(const float4*)(xcol + k * RBLK);
        unsigned long long x0, x1, x2, x3;
        asm("mov.b64 %0, {%1, %1};" : "=l"(x0) : "f"(xv.x));
        asm("mov.b64 %0, {%1, %1};" : "=l"(x1) : "f"(xv.y));
        asm("mov.b64 %0, {%1, %1};" : "=l"(x2) : "f"(xv.z));
        asm("mov.b64 %0, {%1, %1};" : "=l"(x3) : "f"(xv.w));
        const double2* wp = (const double2*)((const char*)wbase + k * 64 * 4);
        #pragma unroll
        for (int q = 0; q < 4; q++) {
            double2 w = wp[q];
            unsigned long long w0 = __double_as_longlong(w.x);
            unsigned long long w1 = __double_as_longlong(w.y);
            asm("fma.rn.f32x2 %0, %1, %2, %0;" : "+l"(acc[0][2*q])   : "l"(x0), "l"(w0));
            asm("fma.rn.f32x2 %0, %1, %2, %0;" : "+l"(acc[0][2*q+1]) : "l"(x0), "l"(w1));
            asm("fma.rn.f32x2 %0, %1, %2, %0;" : "+l"(acc[1][2*q])   : "l"(x1), "l"(w0));
            asm("fma.rn.f32x2 %0, %1, %2, %0;" : "+l"(acc[1][2*q+1]) : "l"(x1), "l"(w1));
            asm("fma.rn.f32x2 %0, %1, %2, %0;" : "+l"(acc[2][2*q])   : "l"(x2), "l"(w0));
            asm("fma.rn.f32x2 %0, %1, %2, %0;" : "+l"(acc[2][2*q+1]) : "l"(x2), "l"(w1));
            asm("fma.rn.f32x2 %0, %1, %2, %0;" : "+l"(acc[3][2*q])   : "l"(x3), "l"(w0));
            asm("fma.rn.f32x2 %0, %1, %2, %0;" : "+l"(acc[3][2*q+1]) : "l"(x3), "l"(w1));
        }
    }

    // Epilogue: relu, store tx_x, logit dot (+4-lane cg reduction)
    #pragma unroll
    for (int row = 0; row < 4; row++) {
        int r = r0 + rq * 4 + row;
        float h[16];
        #pragma unroll
        for (int jj = 0; jj < 8; jj++) {
            float lo, hi;
            asm("mov.b64 {%0, %1}, %2;" : "=f"(lo), "=f"(hi) : "l"(acc[row][jj]));
            h[2 * jj]     = fmaxf(lo, 0.0f);
            h[2 * jj + 1] = fmaxf(hi, 0.0f);
        }
        float partial = 0.0f;
        if (r < N_TX) {
            float4* ox = (float4*)(out + N_TX + (size_t)r * HDIM + cg * 16);
            ox[0] = make_float4(h[0],  h[1],  h[2],  h[3]);
            ox[1] = make_float4(h[4],  h[5],  h[6],  h[7]);
            ox[2] = make_float4(h[8],  h[9],  h[10], h[11]);
            ox[3] = make_float4(h[12], h[13], h[14], h[15]);
            #pragma unroll
            for (int j = 0; j < 16; j++) partial += h[j] * wout_s[cg * 16 + j];
        }
        partial += __shfl_xor_sync(0xffffffffu, partial, 1);
        partial += __shfl_xor_sync(0xffffffffu, partial, 2);
        if (cg == 0 && r < N_TX) out[r] = partial + bout[0];
    }
}

// ---------------------------------------------------------------------------
extern "C" void kernel_launch(void* const* d_in, const int* in_sizes, int n_in,
                              void* d_out, int out_size) {
    const float* x_tx     = (const float*)d_in[0];
    const float* x_acc    = (const float*)d_in[1];
    const int*   pays_src = (const int*)d_in[2];
    const int*   pays_dst = (const int*)d_in[3];
    // d_in[4], d_in[5]: rev edges — dead code in reference (h_acc unused)
    const float* Wl_pays  = (const float*)d_in[6];
    const float* bl_pays  = (const float*)d_in[7];
    const float* Wr_pays  = (const float*)d_in[8];
    // d_in[9..11]: rev weights — unused
    const float* W_out    = (const float*)d_in[12];
    const float* b_out    = (const float*)d_in[13];
    float* out = (float*)d_out;   // [logits(500000) | tx_x(500000*64)]

    const int smem_bytes = (96 * 64 + 96 * RBLK) * sizeof(float);  // 72 KB
    cudaFuncSetAttribute(compute_kernel,
                         cudaFuncAttributeMaxDynamicSharedMemorySize, smem_bytes);

    zero_kernel<<<(N_TX + 255) / 256, 256>>>();
    hist_kernel<<<(NE + 255) / 256, 256>>>(pays_dst);
    scan1_kernel<<<N_SCAN_BLKS, SCAN_BS>>>();
    scan2_kernel<<<1, SCAN_BS>>>();
    scan3_kernel<<<N_SCAN_BLKS, SCAN_BS>>>();
    place_kernel<<<(NE + 255) / 256, 256>>>(pays_src, pays_dst);
    compute_kernel<<<(N_TX + RBLK - 1) / RBLK, CTHREADS, smem_bytes>>>(
        x_tx, x_acc, Wl_pays, bl_pays, Wr_pays, W_out, b_out, out);
}

// round 5
// speedup vs baseline: 3.5568x; 1.4886x over previous
#include <cuda_runtime.h>
#include <cstdint>

#define N_TX   500000
#define N_ACC  100000
#define NE     1000000

#define SCAN_BS   1024
#define N_SCAN_BLKS ((N_TX + SCAN_BS - 1) / SCAN_BS)   // 489

// CSR scratch
__device__ int g_deg[N_TX];
__device__ int g_off[N_TX];      // local-exclusive offsets; bumped to local end by place
__device__ int g_sorted_src[NE];
__device__ int g_bsum[SCAN_BS];

// ---------------------------------------------------------------------------
__global__ void zero_kernel() {
    int i = blockIdx.x * blockDim.x + threadIdx.x;
    if (i < N_TX) g_deg[i] = 0;
}

__global__ void hist_kernel(const int* __restrict__ dst_idx) {
    int e = blockIdx.x * blockDim.x + threadIdx.x;
    if (e < NE) atomicAdd(&g_deg[dst_idx[e]], 1);
}

__global__ void scan1_kernel() {
    __shared__ int sh[SCAN_BS];
    int t = threadIdx.x;
    int idx = blockIdx.x * SCAN_BS + t;
    int v = (idx < N_TX) ? g_deg[idx] : 0;
    sh[t] = v;
    __syncthreads();
    #pragma unroll
    for (int o = 1; o < SCAN_BS; o <<= 1) {
        int add = (t >= o) ? sh[t - o] : 0;
        __syncthreads();
        sh[t] += add;
        __syncthreads();
    }
    if (idx < N_TX) g_off[idx] = sh[t] - v;          // local exclusive
    if (t == SCAN_BS - 1) g_bsum[blockIdx.x] = sh[t];
}

__global__ void scan2_kernel() {
    __shared__ int sh[SCAN_BS];
    int t = threadIdx.x;
    int v = (t < N_SCAN_BLKS) ? g_bsum[t] : 0;
    sh[t] = v;
    __syncthreads();
    #pragma unroll
    for (int o = 1; o < SCAN_BS; o <<= 1) {
        int add = (t >= o) ? sh[t - o] : 0;
        __syncthreads();
        sh[t] += add;
        __syncthreads();
    }
    if (t < N_SCAN_BLKS) g_bsum[t] = sh[t] - v;      // exclusive block bases
}

// place: bump LOCAL offset, add block base (scan3 folded in)
__global__ void place_kernel(const int* __restrict__ src_idx,
                             const int* __restrict__ dst_idx) {
    int e = blockIdx.x * blockDim.x + threadIdx.x;
    if (e >= NE) return;
    int d = dst_idx[e];
    int pos = atomicAdd(&g_off[d], 1) + g_bsum[d >> 10];
    g_sorted_src[pos] = src_idx[e];
}

// ---------------------------------------------------------------------------
// Fused compute kernel: CSR gather-mean + [x|agg][128x96] @ W^T[96x64] via
// mma.sync m16n8k8 tf32 with hi/lo 3-product split; relu + logit epilogue.
// 128 threads (4 warps); warp w owns rows [w*32, w*32+32).
// ---------------------------------------------------------------------------
#define RBLK    128
#define A_STR   100   // floats; bank = 4g + t  -> conflict-free A frags
#define B_STR   72    // floats; bank = 8t + g  -> conflict-free B frags
#define H_STR   68    // restage stride

// dynamic smem floats: A | Bh | Bl
#define SM_A_F  0
#define SM_BH_F (RBLK * A_STR)              // 12800
#define SM_BL_F (SM_BH_F + 96 * B_STR)      // 19712
#define SM_TOT_F (SM_BL_F + 96 * B_STR)     // 26624
#define SMEM_BYTES (SM_TOT_F * 4)           // 106496

__device__ __forceinline__ uint32_t f2tf32(float x) {
    uint32_t r;
    asm("cvt.rna.tf32.f32 %0, %1;" : "=r"(r) : "f"(x));
    return r;
}

__device__ __forceinline__ void mma8(float* c, const uint32_t* a, const uint32_t* b) {
    asm volatile(
        "mma.sync.aligned.m16n8k8.row.col.f32.tf32.tf32.f32 "
        "{%0,%1,%2,%3}, {%4,%5,%6,%7}, {%8,%9}, {%0,%1,%2,%3};"
        : "+f"(c[0]), "+f"(c[1]), "+f"(c[2]), "+f"(c[3])
        : "r"(a[0]), "r"(a[1]), "r"(a[2]), "r"(a[3]), "r"(b[0]), "r"(b[1]));
}

__global__ void __launch_bounds__(128, 2)
compute_kernel(const float* __restrict__ x_tx,
               const float* __restrict__ x_acc,
               const float* __restrict__ Wl,   // [32,64]
               const float* __restrict__ bl,   // [64]
               const float* __restrict__ Wr,   // [64,64]
               const float* __restrict__ Wout, // [64]
               const float* __restrict__ bout, // [1]
               float* __restrict__ out) {
    extern __shared__ float smem[];
    float*    As = smem + SM_A_F;
    uint32_t* Bh = (uint32_t*)(smem + SM_BH_F);
    uint32_t* Blo = (uint32_t*)(smem + SM_BL_F);
    __shared__ float bl_s[64];
    __shared__ float wout_s[64];

    const int tid  = threadIdx.x;
    const int wid  = tid >> 5;
    const int lane = tid & 31;
    const int r0   = blockIdx.x * RBLK;

    if (tid < 64) { bl_s[tid] = bl[tid]; wout_s[tid] = Wout[tid]; }

    // ---- Stage A = [x_tx | agg_mean], row-major stride A_STR ----
    {
        const int r = r0 + tid;
        float* Arow = As + tid * A_STR;
        if (r < N_TX) {
            const float4* xr = (const float4*)(x_tx + (size_t)r * 64);
            #pragma unroll
            for (int j = 0; j < 16; j++) ((float4*)Arow)[j] = xr[j];
        } else {
            float4 z = make_float4(0.f, 0.f, 0.f, 0.f);
            #pragma unroll
            for (int j = 0; j < 16; j++) ((float4*)Arow)[j] = z;
        }

        // CSR gather-mean
        float a[32];
        #pragma unroll
        for (int d = 0; d < 32; d++) a[d] = 0.f;
        int cnt = 0;
        if (r < N_TX) {
            cnt = g_deg[r];
            int end = g_off[r] + g_bsum[r >> 10];
            int start = end - cnt;
            for (int i = 0; i < cnt; i++) {
                int s = g_sorted_src[start + i];
                const float4* p = (const float4*)(x_acc + (size_t)s * 32);
                #pragma unroll
                for (int j = 0; j < 8; j++) {
                    float4 v = p[j];
                    a[j * 4 + 0] += v.x; a[j * 4 + 1] += v.y;
                    a[j * 4 + 2] += v.z; a[j * 4 + 3] += v.w;
                }
            }
        }
        float inv = 1.f / (float)max(cnt, 1);
        #pragma unroll
        for (int d = 0; d < 32; d++) Arow[64 + d] = a[d] * inv;
    }

    // ---- Stage B = W^T [96 k][64 n], hi/lo tf32 split ----
    {
        const int n  = tid & 63;
        const int k0 = (tid >> 6) * 48;
        for (int kk = 0; kk < 48; kk++) {
            int k = k0 + kk;
            float w = (k < 64) ? Wr[k * 64 + n] : Wl[(k - 64) * 64 + n];
            uint32_t hi = f2tf32(w);
            uint32_t lo = f2tf32(w - __uint_as_float(hi));
            Bh[k * B_STR + n]  = hi;
            Blo[k * B_STR + n] = lo;
        }
    }
    __syncthreads();

    const int t = lane & 3;    // col within A frag / k within B frag
    const int g = lane >> 2;   // row group
    const int rb = wid * 32;   // warp row base

    // Accumulators [mtile][ntile][4], seeded with bias
    float acc[2][8][4];
    #pragma unroll
    for (int nt = 0; nt < 8; nt++) {
        float b0 = bl_s[nt * 8 + t * 2];
        float b1 = bl_s[nt * 8 + t * 2 + 1];
        #pragma unroll
        for (int mt = 0; mt < 2; mt++) {
            acc[mt][nt][0] = b0; acc[mt][nt][1] = b1;
            acc[mt][nt][2] = b0; acc[mt][nt][3] = b1;
        }
    }

    #pragma unroll 4
    for (int kt = 0; kt < 12; kt++) {
        const int k0 = kt * 8;
        uint32_t ahi[2][4], alo[2][4];
        #pragma unroll
        for (int mt = 0; mt < 2; mt++) {
            const float* Ar = As + (rb + mt * 16 + g) * A_STR + k0 + t;
            float f0 = Ar[0];
            float f2 = Ar[4];
            float f1 = Ar[8 * A_STR];
            float f3 = Ar[8 * A_STR + 4];
            ahi[mt][0] = f2tf32(f0); alo[mt][0] = f2tf32(f0 - __uint_as_float(ahi[mt][0]));
            ahi[mt][1] = f2tf32(f1); alo[mt][1] = f2tf32(f1 - __uint_as_float(ahi[mt][1]));
            ahi[mt][2] = f2tf32(f2); alo[mt][2] = f2tf32(f2 - __uint_as_float(ahi[mt][2]));
            ahi[mt][3] = f2tf32(f3); alo[mt][3] = f2tf32(f3 - __uint_as_float(ahi[mt][3]));
        }
        #pragma unroll
        for (int nt = 0; nt < 8; nt++) {
            const int n = nt * 8 + g;
            uint32_t bh[2], blv[2];
            bh[0]  = Bh[(k0 + t) * B_STR + n];
            bh[1]  = Bh[(k0 + t + 4) * B_STR + n];
            blv[0] = Blo[(k0 + t) * B_STR + n];
            blv[1] = Blo[(k0 + t + 4) * B_STR + n];
            mma8(acc[0][nt], ahi[0], bh);
            mma8(acc[0][nt], alo[0], bh);
            mma8(acc[0][nt], ahi[0], blv);
            mma8(acc[1][nt], ahi[1], bh);
            mma8(acc[1][nt], alo[1], bh);
            mma8(acc[1][nt], ahi[1], blv);
        }
    }
    __syncthreads();   // done reading As; reuse as restage buffer

    // ---- Epilogue: relu + logit dot + restage ----
    #pragma unroll
    for (int mt = 0; mt < 2; mt++) {
        #pragma unroll
        for (int half = 0; half < 2; half++) {
            const int row = rb + mt * 16 + half * 8 + g;
            float* hrow = smem + row * H_STR;
            float partial = 0.f;
            #pragma unroll
            for (int nt = 0; nt < 8; nt++) {
                float h0 = fmaxf(acc[mt][nt][half * 2 + 0], 0.f);
                float h1 = fmaxf(acc[mt][nt][half * 2 + 1], 0.f);
                int col = nt * 8 + t * 2;
                partial += h0 * wout_s[col] + h1 * wout_s[col + 1];
                *(float2*)(hrow + col) = make_float2(h0, h1);
            }
            partial += __shfl_xor_sync(0xffffffffu, partial, 1);
            partial += __shfl_xor_sync(0xffffffffu, partial, 2);
            int r = r0 + row;
            if (t == 0 && r < N_TX) out[r] = partial + bout[0];
        }
    }
    __syncthreads();

    // ---- Coalesced tx_x store ----
    {
        const int vr = (N_TX - r0 < RBLK) ? (N_TX - r0) : RBLK;
        float4* dst = (float4*)(out + N_TX + (size_t)r0 * 64);
        #pragma unroll
        for (int i = tid; i < RBLK * 16; i += 128) {
            int row = i >> 4, c = i & 15;
            if (row < vr)
                dst[row * 16 + c] = *(float4*)(smem + row * H_STR + c * 4);
        }
    }
}

// ---------------------------------------------------------------------------
extern "C" void kernel_launch(void* const* d_in, const int* in_sizes, int n_in,
                              void* d_out, int out_size) {
    const float* x_tx     = (const float*)d_in[0];
    const float* x_acc    = (const float*)d_in[1];
    const int*   pays_src = (const int*)d_in[2];
    const int*   pays_dst = (const int*)d_in[3];
    // d_in[4], d_in[5]: rev edges — dead code in reference (h_acc unused)
    const float* Wl_pays  = (const float*)d_in[6];
    const float* bl_pays  = (const float*)d_in[7];
    const float* Wr_pays  = (const float*)d_in[8];
    // d_in[9..11]: rev weights — unused
    const float* W_out    = (const float*)d_in[12];
    const float* b_out    = (const float*)d_in[13];
    float* out = (float*)d_out;   // [logits(500000) | tx_x(500000*64)]

    cudaFuncSetAttribute(compute_kernel,
                         cudaFuncAttributeMaxDynamicSharedMemorySize, SMEM_BYTES);

    zero_kernel<<<(N_TX + 255) / 256, 256>>>();
    hist_kernel<<<(NE + 255) / 256, 256>>>(pays_dst);
    scan1_kernel<<<N_SCAN_BLKS, SCAN_BS>>>();
    scan2_kernel<<<1, SCAN_BS>>>();
    place_kernel<<<(NE + 255) / 256, 256>>>(pays_src, pays_dst);
    compute_kernel<<<(N_TX + RBLK - 1) / RBLK, RBLK, SMEM_BYTES>>>(
        x_tx, x_acc, Wl_pays, bl_pays, Wr_pays, W_out, b_out, out);
}

// round 7
// speedup vs baseline: 4.2981x; 1.2084x over previous
#include <cuda_runtime.h>
#include <cstdint>

#define N_TX   500000
#define N_ACC  100000
#define NE     1000000

#define SCAN_BS   1024
#define N_SCAN_BLKS ((N_TX + SCAN_BS - 1) / SCAN_BS)   // 489

// CSR scratch
__device__ int g_deg[N_TX];
__device__ int g_off[N_TX];      // local-exclusive offsets; bumped by place
__device__ int g_sorted_src[NE];
__device__ int g_bsum[SCAN_BS];

// ---------------------------------------------------------------------------
__global__ void zero_kernel() {
    int i = blockIdx.x * blockDim.x + threadIdx.x;
    if (i < N_TX) g_deg[i] = 0;
}

__global__ void hist_kernel(const int* __restrict__ dst_idx) {
    int e = blockIdx.x * blockDim.x + threadIdx.x;
    if (e < NE) atomicAdd(&g_deg[dst_idx[e]], 1);
}

__global__ void scan1_kernel() {
    __shared__ int sh[SCAN_BS];
    int t = threadIdx.x;
    int idx = blockIdx.x * SCAN_BS + t;
    int v = (idx < N_TX) ? g_deg[idx] : 0;
    sh[t] = v;
    __syncthreads();
    #pragma unroll
    for (int o = 1; o < SCAN_BS; o <<= 1) {
        int add = (t >= o) ? sh[t - o] : 0;
        __syncthreads();
        sh[t] += add;
        __syncthreads();
    }
    if (idx < N_TX) g_off[idx] = sh[t] - v;
    if (t == SCAN_BS - 1) g_bsum[blockIdx.x] = sh[t];
}

__global__ void scan2_kernel() {
    __shared__ int sh[SCAN_BS];
    int t = threadIdx.x;
    int v = (t < N_SCAN_BLKS) ? g_bsum[t] : 0;
    sh[t] = v;
    __syncthreads();
    #pragma unroll
    for (int o = 1; o < SCAN_BS; o <<= 1) {
        int add = (t >= o) ? sh[t - o] : 0;
        __syncthreads();
        sh[t] += add;
        __syncthreads();
    }
    if (t < N_SCAN_BLKS) g_bsum[t] = sh[t] - v;
}

__global__ void place_kernel(const int* __restrict__ src_idx,
                             const int* __restrict__ dst_idx) {
    int e = blockIdx.x * blockDim.x + threadIdx.x;
    if (e >= NE) return;
    int d = dst_idx[e];
    int pos = atomicAdd(&g_off[d], 1) + g_bsum[d >> 10];
    g_sorted_src[pos] = src_idx[e];
}

// ---------------------------------------------------------------------------
// Fused compute kernel: CSR gather-mean + [x|agg][128x96] @ W^T[96x64] via
// mma.sync m16n8k16 bf16 with hi/lo 3-product split (operands pre-packed in
// SMEM as bf16x2); relu + logit epilogue. 128 threads, 4 warps, warp = 32 rows.
// ---------------------------------------------------------------------------
#define RBLK   128
#define A_STR  52    // u32/row (need >=48). 52%32==20 -> frag bank=(20g+t): bijective
#define B_STR  72    // u32; 72%32==8 -> frag bank = 8t+g, bijective
#define H_STR  68    // restage stride (floats)

// dynamic smem (u32 units): Ahi | Alo | Bh | Bl
#define SM_AHI 0
#define SM_ALO (RBLK * A_STR)                 // 6656
#define SM_BH  (SM_ALO + RBLK * A_STR)        // 13312
#define SM_BL  (SM_BH + 48 * B_STR)           // 16768
#define SM_TOT (SM_BL + 48 * B_STR)           // 20224 u32
#define SMEM_BYTES (SM_TOT * 4)               // 80896 B

// pack two f32 into bf16x2 hi + residual lo (first PTX source -> HIGH half,
// so v0 lands in the LOW half = even-k element)
__device__ __forceinline__ void pack_pair(float v0, float v1,
                                          uint32_t& hi, uint32_t& lo) {
    uint32_t h;
    asm("cvt.rn.bf16x2.f32 %0, %1, %2;" : "=r"(h) : "f"(v1), "f"(v0));
    float f0 = __uint_as_float(h << 16);
    float f1 = __uint_as_float(h & 0xffff0000u);
    float r0 = v0 - f0, r1 = v1 - f1;
    uint32_t l;
    asm("cvt.rn.bf16x2.f32 %0, %1, %2;" : "=r"(l) : "f"(r1), "f"(r0));
    hi = h; lo = l;
}

__device__ __forceinline__ void mma16(float* c, const uint32_t* a, const uint32_t* b) {
    asm volatile(
        "mma.sync.aligned.m16n8k16.row.col.f32.bf16.bf16.f32 "
        "{%0,%1,%2,%3}, {%4,%5,%6,%7}, {%8,%9}, {%0,%1,%2,%3};"
        : "+f"(c[0]), "+f"(c[1]), "+f"(c[2]), "+f"(c[3])
        : "r"(a[0]), "r"(a[1]), "r"(a[2]), "r"(a[3]), "r"(b[0]), "r"(b[1]));
}

__global__ void __launch_bounds__(128, 2)
compute_kernel(const float* __restrict__ x_tx,
               const float* __restrict__ x_acc,
               const float* __restrict__ Wl,   // [32,64]
               const float* __restrict__ bl,   // [64]
               const float* __restrict__ Wr,   // [64,64]
               const float* __restrict__ Wout, // [64]
               const float* __restrict__ bout, // [1]
               float* __restrict__ out) {
    extern __shared__ uint32_t smem_u32[];
    uint32_t* Ahi = smem_u32 + SM_AHI;
    uint32_t* Alo = smem_u32 + SM_ALO;
    uint32_t* Bh  = smem_u32 + SM_BH;
    uint32_t* Blo = smem_u32 + SM_BL;
    float* restage = (float*)smem_u32;   // reused after GEMM (fits in A region)
    __shared__ float bl_s[64];
    __shared__ float wout_s[64];

    const int tid  = threadIdx.x;
    const int wid  = tid >> 5;
    const int lane = tid & 31;
    const int r0   = blockIdx.x * RBLK;

    if (tid < 64) { bl_s[tid] = bl[tid]; wout_s[tid] = Wout[tid]; }

    // ---- Stage A row (thread = row): x_tx -> kp 0..31, agg -> kp 32..47 ----
    {
        const int r = r0 + tid;
        uint32_t* AhiR = Ahi + tid * A_STR;
        uint32_t* AloR = Alo + tid * A_STR;

        if (r < N_TX) {
            const float4* xr = (const float4*)(x_tx + (size_t)r * 64);
            #pragma unroll
            for (int j = 0; j < 16; j++) {
                float4 v = xr[j];
                uint32_t h0, l0, h1, l1;
                pack_pair(v.x, v.y, h0, l0);
                pack_pair(v.z, v.w, h1, l1);
                AhiR[j * 2] = h0; AhiR[j * 2 + 1] = h1;
                AloR[j * 2] = l0; AloR[j * 2 + 1] = l1;
            }
        } else {
            #pragma unroll
            for (int j = 0; j < 32; j++) { AhiR[j] = 0u; AloR[j] = 0u; }
        }

        // CSR gather-mean
        float a[32];
        #pragma unroll
        for (int d = 0; d < 32; d++) a[d] = 0.f;
        int cnt = 0;
        if (r < N_TX) {
            cnt = g_deg[r];
            int end = g_off[r] + g_bsum[r >> 10];
            int start = end - cnt;
            for (int i = 0; i < cnt; i++) {
                int s = g_sorted_src[start + i];
                const float4* p = (const float4*)(x_acc + (size_t)s * 32);
                #pragma unroll
                for (int j = 0; j < 8; j++) {
                    float4 v = p[j];
                    a[j * 4 + 0] += v.x; a[j * 4 + 1] += v.y;
                    a[j * 4 + 2] += v.z; a[j * 4 + 3] += v.w;
                }
            }
        }
        float inv = 1.f / (float)max(cnt, 1);
        #pragma unroll
        for (int j = 0; j < 16; j++) {
            uint32_t h, l;
            pack_pair(a[j * 2] * inv, a[j * 2 + 1] * inv, h, l);
            AhiR[32 + j] = h;
            AloR[32 + j] = l;
        }
    }

    // ---- Stage B = W^T [96 k][64 n] as bf16x2 k-pairs, hi/lo ----
    {
        const int n   = tid & 63;
        const int kp0 = (tid >> 6) * 24;   // 24 k-pairs per half
        for (int kp = kp0; kp < kp0 + 24; kp++) {
            int k0 = kp * 2;
            float w0 = (k0 < 64) ? Wr[k0 * 64 + n] : Wl[(k0 - 64) * 64 + n];
            int k1 = k0 + 1;
            float w1 = (k1 < 64) ? Wr[k1 * 64 + n] : Wl[(k1 - 64) * 64 + n];
            uint32_t h, l;
            pack_pair(w0, w1, h, l);
            Bh[kp * B_STR + n]  = h;
            Blo[kp * B_STR + n] = l;
        }
    }
    __syncthreads();

    const int t  = lane & 3;
    const int g  = lane >> 2;
    const int rb = wid * 32;

    // Accumulators [mtile][ntile][4], seeded with bias
    float acc[2][8][4];
    #pragma unroll
    for (int nt = 0; nt < 8; nt++) {
        float b0 = bl_s[nt * 8 + t * 2];
        float b1 = bl_s[nt * 8 + t * 2 + 1];
        #pragma unroll
        for (int mt = 0; mt < 2; mt++) {
            acc[mt][nt][0] = b0; acc[mt][nt][1] = b1;
            acc[mt][nt][2] = b0; acc[mt][nt][3] = b1;
        }
    }

    #pragma unroll
    for (int kt = 0; kt < 6; kt++) {
        const int kp0 = kt * 8;
        uint32_t ahi[2][4], alo[2][4];
        #pragma unroll
        for (int mt = 0; mt < 2; mt++) {
            const uint32_t* Ah = Ahi + (rb + mt * 16 + g) * A_STR + kp0 + t;
            const uint32_t* Al = Alo + (rb + mt * 16 + g) * A_STR + kp0 + t;
            ahi[mt][0] = Ah[0];                 // (row g,    kp t)
            ahi[mt][1] = Ah[8 * A_STR];         // (row g+8,  kp t)
            ahi[mt][2] = Ah[4];                 // (row g,    kp t+4)
            ahi[mt][3] = Ah[8 * A_STR + 4];     // (row g+8,  kp t+4)
            alo[mt][0] = Al[0];
            alo[mt][1] = Al[8 * A_STR];
            alo[mt][2] = Al[4];
            alo[mt][3] = Al[8 * A_STR + 4];
        }
        #pragma unroll
        for (int nt = 0; nt < 8; nt++) {
            const int n = nt * 8 + g;
            const uint32_t* Bp = Bh  + (kp0 + t) * B_STR + n;
            const uint32_t* Lp = Blo + (kp0 + t) * B_STR + n;
            uint32_t bh[2], blv[2];
            bh[0]  = Bp[0];
            bh[1]  = Bp[4 * B_STR];
            blv[0] = Lp[0];
            blv[1] = Lp[4 * B_STR];
            mma16(acc[0][nt], ahi[0], bh);
            mma16(acc[0][nt], alo[0], bh);
            mma16(acc[0][nt], ahi[0], blv);
            mma16(acc[1][nt], ahi[1], bh);
            mma16(acc[1][nt], alo[1], bh);
            mma16(acc[1][nt], ahi[1], blv);
        }
    }
    __syncthreads();   // done reading A/B; reuse smem as restage buffer

    // ---- Epilogue: relu + logit dot + restage ----
    #pragma unroll
    for (int mt = 0; mt < 2; mt++) {
        #pragma unroll
        for (int half = 0; half < 2; half++) {
            const int row = rb + mt * 16 + half * 8 + g;
            float* hrow = restage + row * H_STR;
            float partial = 0.f;
            #pragma unroll
            for (int nt = 0; nt < 8; nt++) {
                float h0 = fmaxf(acc[mt][nt][half * 2 + 0], 0.f);
                float h1 = fmaxf(acc[mt][nt][half * 2 + 1], 0.f);
                int col = nt * 8 + t * 2;
                partial += h0 * wout_s[col] + h1 * wout_s[col + 1];
                *(float2*)(hrow + col) = make_float2(h0, h1);
            }
            partial += __shfl_xor_sync(0xffffffffu, partial, 1);
            partial += __shfl_xor_sync(0xffffffffu, partial, 2);
            int r = r0 + row;
            if (t == 0 && r < N_TX) out[r] = partial + bout[0];
        }
    }
    __syncthreads();

    // ---- Coalesced tx_x store ----
    {
        const int vr = (N_TX - r0 < RBLK) ? (N_TX - r0) : RBLK;
        float4* dst = (float4*)(out + N_TX + (size_t)r0 * 64);
        #pragma unroll
        for (int i = tid; i < RBLK * 16; i += 128) {
            int row = i >> 4, c = i & 15;
            if (row < vr)
                dst[row * 16 + c] = *(float4*)(restage + row * H_STR + c * 4);
        }
    }
}

// ---------------------------------------------------------------------------
extern "C" void kernel_launch(void* const* d_in, const int* in_sizes, int n_in,
                              void* d_out, int out_size) {
    const float* x_tx     = (const float*)d_in[0];
    const float* x_acc    = (const float*)d_in[1];
    const int*   pays_src = (const int*)d_in[2];
    const int*   pays_dst = (const int*)d_in[3];
    // d_in[4], d_in[5]: rev edges — dead code in reference (h_acc unused)
    const float* Wl_pays  = (const float*)d_in[6];
    const float* bl_pays  = (const float*)d_in[7];
    const float* Wr_pays  = (const float*)d_in[8];
    // d_in[9..11]: rev weights — unused
    const float* W_out    = (const float*)d_in[12];
    const float* b_out    = (const float*)d_in[13];
    float* out = (float*)d_out;   // [logits(500000) | tx_x(500000*64)]

    cudaFuncSetAttribute(compute_kernel,
                         cudaFuncAttributeMaxDynamicSharedMemorySize, SMEM_BYTES);

    zero_kernel<<<(N_TX + 255) / 256, 256>>>();
    hist_kernel<<<(NE + 255) / 256, 256>>>(pays_dst);
    scan1_kernel<<<N_SCAN_BLKS, SCAN_BS>>>();
    scan2_kernel<<<1, SCAN_BS>>>();
    place_kernel<<<(NE + 255) / 256, 256>>>(pays_src, pays_dst);
    compute_kernel<<<(N_TX + RBLK - 1) / RBLK, RBLK, SMEM_BYTES>>>(
        x_tx, x_acc, Wl_pays, bl_pays, Wr_pays, W_out, b_out, out);
}